// round 12
// baseline (speedup 1.0000x reference)
#include <cuda_runtime.h>
#include <cuda_fp16.h>
#include <cstdint>

#define N_Q   8192
#define DIM   384
#define N_DOC 1024
#define KST   384           // fp16 hi only, both operands
#define K_ITERS 6           // 6 chunks of 64

// ---------------- scratch (static device globals; no allocation) -------------
__device__ float   g_C[(size_t)N_DOC * DIM];
__device__ float   g_den[N_DOC];
__device__ __half  g_A2[(size_t)N_Q  * KST];    // 6.3 MB
__device__ __half  g_B2[(size_t)N_DOC * KST];   // 0.8 MB
__device__ float   g_G[(size_t)N_Q * N_DOC];    // 33.5 MB

// ---------------- helpers -----------------------------------------------------
__device__ __forceinline__ uint32_t smem_u32(const void* p) {
    uint32_t a;
    asm("{ .reg .u64 t; cvta.to.shared.u64 t, %1; cvt.u32.u64 %0, t; }" : "=r"(a) : "l"(p));
    return a;
}
__device__ __forceinline__ void cp16(uint32_t dst, const void* src) {
    asm volatile("cp.async.cg.shared.global [%0], [%1], 16;" :: "r"(dst), "l"(src));
}
__device__ __forceinline__ void cp_commit() { asm volatile("cp.async.commit_group;"); }
__device__ __forceinline__ void ldsm4(uint32_t& r0, uint32_t& r1, uint32_t& r2, uint32_t& r3,
                                      uint32_t addr) {
    asm volatile("ldmatrix.sync.aligned.m8n8.x4.shared.b16 {%0,%1,%2,%3}, [%4];"
                 : "=r"(r0), "=r"(r1), "=r"(r2), "=r"(r3) : "r"(addr));
}
__device__ __forceinline__ void mma16816(float* c, const uint32_t* a, const uint32_t* b) {
    asm volatile(
        "mma.sync.aligned.m16n8k16.row.col.f32.f16.f16.f32 "
        "{%0,%1,%2,%3}, {%4,%5,%6,%7}, {%8,%9}, {%0,%1,%2,%3};"
        : "+f"(c[0]), "+f"(c[1]), "+f"(c[2]), "+f"(c[3])
        : "r"(a[0]), "r"(a[1]), "r"(a[2]), "r"(a[3]), "r"(b[0]), "r"(b[1]));
}

// ---------------- kernel 0: zero the segment accumulators --------------------
__global__ void k_zero() {
    int idx = blockIdx.x * 256 + threadIdx.x;
    if (idx < N_DOC * DIM) g_C[idx] = 0.0f;
    if (idx < N_DOC)       g_den[idx] = 0.0f;
}

// ---------------- kernel 1: normalize + write A2 (fp16) + segment acc --------
__global__ __launch_bounds__(128) void k_norm_acc(
    const float* __restrict__ emb, const float* __restrict__ label,
    const int* __restrict__ did)
{
    int i = blockIdx.x;
    int t = threadIdx.x;
    const float* row = emb + (size_t)i * DIM;
    float v0 = row[t], v1 = row[t + 128], v2 = row[t + 256];
    float ss = v0 * v0 + v1 * v1 + v2 * v2;
    #pragma unroll
    for (int o = 16; o > 0; o >>= 1) ss += __shfl_xor_sync(0xFFFFFFFFu, ss, o);
    __shared__ float sred[4];
    if ((t & 31) == 0) sred[t >> 5] = ss;
    __syncthreads();
    float inv = rsqrtf(sred[0] + sred[1] + sred[2] + sred[3]);

    float q[3] = { v0 * inv, v1 * inv, v2 * inv };
    __half* arow = g_A2 + (size_t)i * KST;
    #pragma unroll
    for (int s = 0; s < 3; ++s)
        arow[t + s * 128] = __float2half(q[s]);

    float w = label[i];
    int   j = did[i];
    float* crow = g_C + (size_t)j * DIM;
    atomicAdd(&crow[t],       w * q[0]);
    atomicAdd(&crow[t + 128], w * q[1]);
    atomicAdd(&crow[t + 256], w * q[2]);
    if (t == 0) atomicAdd(&g_den[j], w);
}

// ---------------- kernel 2: B2 = fp16(C/den) ----------------------------------
__global__ __launch_bounds__(128) void k_scale() {
    int j = blockIdx.x;
    float inv = 1.0f / g_den[j];
    const float* crow = g_C + (size_t)j * DIM;
    __half* brow = g_B2 + (size_t)j * KST;
    for (int d = threadIdx.x; d < DIM; d += 128)
        brow[d] = __float2half(crow[d] * inv);
}

// ---------------- kernel 3: HMMA GEMM  G = A2 * B2^T (pure fp16) --------------
// 128x128 CTA tile, 4 warps (2x2), warp tile 64x64, BK=64,
// 3-stage cp.async pipeline, one __syncthreads per chunk.
// Rows 144B (128 data + 16 pad): (r*144)%128 = 16r%128 -> ldmatrix conflict-free.
#define BK        64
#define ROWB      144
#define STAGE_SB  (128 * ROWB)              // 18432 B per matrix per stage
#define STAGES    3
#define SM_TOTAL  (2 * STAGES * STAGE_SB)   // 110592 B

__device__ __forceinline__ void issue_stage(
    int s, int buf, int tid, uint32_t sAu, uint32_t sBu,
    const __half* Abase, const __half* Bbase)
{
    int k0 = s * BK;
    uint32_t ad = sAu + buf * STAGE_SB;
    uint32_t bd = sBu + buf * STAGE_SB;
    #pragma unroll
    for (int j = 0; j < 8; ++j) {
        int idx = tid + j * 128;
        int r = idx >> 3, c = idx & 7;
        cp16(ad + r * ROWB + c * 16, Abase + (size_t)r * KST + k0 + c * 8);
        cp16(bd + r * ROWB + c * 16, Bbase + (size_t)r * KST + k0 + c * 8);
    }
    cp_commit();
}

__global__ __launch_bounds__(128, 2) void k_gemm() {
    extern __shared__ __align__(128) char smem[];
    uint32_t sAu = smem_u32(smem);
    uint32_t sBu = sAu + STAGES * STAGE_SB;

    int tid  = threadIdx.x;
    int lane = tid & 31;
    int wid  = tid >> 5;
    int wm   = wid >> 1;             // 0..1 -> 64 rows
    int wn   = wid & 1;              // 0..1 -> 64 cols
    int tm = blockIdx.x;             // 0..63
    int tn = blockIdx.y;             // 0..7

    const __half* Abase = g_A2 + (size_t)(tm * 128) * KST;
    const __half* Bbase = g_B2 + (size_t)(tn * 128) * KST;

    float acc[4][8][4];
    #pragma unroll
    for (int i = 0; i < 4; i++)
        #pragma unroll
        for (int j = 0; j < 8; j++)
            #pragma unroll
            for (int v = 0; v < 4; v++) acc[i][j][v] = 0.0f;

    issue_stage(0, 0, tid, sAu, sBu, Abase, Bbase);
    issue_stage(1, 1, tid, sAu, sBu, Abase, Bbase);

    // fragment addressing
    int a_row = wm * 64 + (lane & 15);                      // + mi*16
    int a_off = (lane >> 4) * 16;
    int b_row = wn * 64 + ((lane >> 4) * 8 + (lane & 7));   // + nt2*16
    int b_off = ((lane >> 3) & 1) * 16;

    #pragma unroll 1
    for (int it = 0; it < K_ITERS; ++it) {
        int buf = it % STAGES;

        // After this wait, stage `it` is guaranteed landed. For the last two
        // iterations nothing new is issued, so drain fully (wait_group 0);
        // earlier iterations keep one group (stage it+1) in flight.
        if (it + 2 < K_ITERS)
            asm volatile("cp.async.wait_group 1;");
        else
            asm volatile("cp.async.wait_group 0;");
        __syncthreads();

        if (it + 2 < K_ITERS)
            issue_stage(it + 2, (it + 2) % STAGES, tid, sAu, sBu, Abase, Bbase);

        uint32_t sab = sAu + buf * STAGE_SB;
        uint32_t sbb = sBu + buf * STAGE_SB;

        #pragma unroll
        for (int kk = 0; kk < 4; ++kk) {
            uint32_t a[4][4];
            #pragma unroll
            for (int mi = 0; mi < 4; ++mi)
                ldsm4(a[mi][0], a[mi][1], a[mi][2], a[mi][3],
                      sab + (a_row + mi * 16) * ROWB + kk * 32 + a_off);
            uint32_t b[8][2];
            #pragma unroll
            for (int nt2 = 0; nt2 < 4; ++nt2) {
                uint32_t r0, r1, r2, r3;
                ldsm4(r0, r1, r2, r3,
                      sbb + (b_row + nt2 * 16) * ROWB + kk * 32 + b_off);
                b[nt2 * 2][0] = r0;     b[nt2 * 2][1] = r1;
                b[nt2 * 2 + 1][0] = r2; b[nt2 * 2 + 1][1] = r3;
            }
            #pragma unroll
            for (int mi = 0; mi < 4; ++mi)
                #pragma unroll
                for (int nj = 0; nj < 8; ++nj)
                    mma16816(acc[mi][nj], a[mi], b[nj]);
        }
    }

    // ---- epilogue: write 64x64 warp tile
    int rbase = tm * 128 + wm * 64 + (lane >> 2);
    int cbase = tn * 128 + wn * 64 + (lane & 3) * 2;
    #pragma unroll
    for (int mi = 0; mi < 4; ++mi) {
        #pragma unroll
        for (int nj = 0; nj < 8; ++nj) {
            int r = rbase + mi * 16;
            int c = cbase + nj * 8;
            *(float2*)(g_G + (size_t)r * N_DOC + c) =
                make_float2(acc[mi][nj][0], acc[mi][nj][1]);
            *(float2*)(g_G + (size_t)(r + 8) * N_DOC + c) =
                make_float2(acc[mi][nj][2], acc[mi][nj][3]);
        }
    }
}

// ---------------- kernel 4: theta[i,q] = G[i, did[q]] — 4-row packed gather ---
// sG4[j] packs G[i0..i0+3][j] as float4: one LDS.128 gather serves 4 output rows.
#define EXP_ROWS 16      // 4 groups of 4 rows per block
__global__ __launch_bounds__(512) void k_expand(const int* __restrict__ did,
                                                float* __restrict__ out)
{
    __shared__ int    sdid[N_Q];    // 32 KB
    __shared__ float4 sG4[N_DOC];   // 16 KB
    int t = threadIdx.x;
    for (int q = t; q < N_Q; q += 512) sdid[q] = did[q];

    int i00 = blockIdx.x * EXP_ROWS;
    #pragma unroll 1
    for (int g = 0; g < EXP_ROWS / 4; ++g) {
        int i0 = i00 + g * 4;
        __syncthreads();   // guards sdid (g==0) and sG4 reuse (g>0)
        for (int j = t; j < N_DOC; j += 512) {
            sG4[j] = make_float4(g_G[(size_t)(i0 + 0) * N_DOC + j],
                                 g_G[(size_t)(i0 + 1) * N_DOC + j],
                                 g_G[(size_t)(i0 + 2) * N_DOC + j],
                                 g_G[(size_t)(i0 + 3) * N_DOC + j]);
        }
        __syncthreads();

        const int4* sdid4 = (const int4*)sdid;
        float* o0 = out + (size_t)(i0 + 0) * N_Q;
        float* o1 = out + (size_t)(i0 + 1) * N_Q;
        float* o2 = out + (size_t)(i0 + 2) * N_Q;
        float* o3 = out + (size_t)(i0 + 3) * N_Q;
        #pragma unroll 2
        for (int q4 = t; q4 < N_Q / 4; q4 += 512) {
            int4 d4 = sdid4[q4];
            float4 f0 = sG4[d4.x];
            float4 f1 = sG4[d4.y];
            float4 f2 = sG4[d4.z];
            float4 f3 = sG4[d4.w];
            ((float4*)o0)[q4] = make_float4(f0.x, f1.x, f2.x, f3.x);
            ((float4*)o1)[q4] = make_float4(f0.y, f1.y, f2.y, f3.y);
            ((float4*)o2)[q4] = make_float4(f0.z, f1.z, f2.z, f3.z);
            ((float4*)o3)[q4] = make_float4(f0.w, f1.w, f2.w, f3.w);
        }
    }
}

// ---------------- launch ------------------------------------------------------
extern "C" void kernel_launch(void* const* d_in, const int* in_sizes, int n_in,
                              void* d_out, int out_size)
{
    const float* emb   = (const float*)d_in[0];
    const float* label = (const float*)d_in[1];
    const int*   did   = (const int*)d_in[2];
    float*       out   = (float*)d_out;

    cudaFuncSetAttribute(k_gemm, cudaFuncAttributeMaxDynamicSharedMemorySize, SM_TOTAL);

    k_zero<<<(N_DOC * DIM + 255) / 256, 256>>>();
    k_norm_acc<<<N_Q, 128>>>(emb, label, did);
    k_scale<<<N_DOC, 128>>>();
    k_gemm<<<dim3(64, 8), 128, SM_TOTAL>>>();
    k_expand<<<N_Q / EXP_ROWS, 512>>>(did, out);
}